// round 9
// baseline (speedup 1.0000x reference)
#include <cuda_runtime.h>
#include <cuda_fp16.h>
#include <cstdint>

#define D      128      // D_IN = D_OUT
#define NMAX   100000
#define EMAX   1600000

// Scratch (device globals; no allocation allowed)
__device__ __half g_xh[NMAX * D];   // x rounded to fp16 (GEMM A operand)
__device__ __half g_yh[NMAX * D];   // y = x @ W2, stored fp16
__device__ int    g_count [NMAX];   // edges per DST
__device__ int    g_off   [NMAX];   // CSR row offsets (by dst)
__device__ int    g_cursor[NMAX];   // fill cursors
__device__ uint2  g_edges [EMAX];   // dst-sorted (src, val_bits)

// ============================================================================
// PTX helpers (base ISA: cp.async / ldmatrix / mma.sync)
// ============================================================================
__device__ __forceinline__ uint32_t smem_to_u32(const void* p) {
    uint32_t a;
    asm("{ .reg .u64 t; cvta.to.shared.u64 t, %1; cvt.u32.u64 %0, t; }"
        : "=r"(a) : "l"(p));
    return a;
}
#define CP_ASYNC16(dst, src, sz) \
    asm volatile("cp.async.cg.shared.global [%0], [%1], 16, %2;" \
        :: "r"(dst), "l"(src), "r"(sz))
#define CP_COMMIT() asm volatile("cp.async.commit_group;" ::: "memory")
#define CP_WAIT1()  asm volatile("cp.async.wait_group 1;"  ::: "memory")

#define LDSM_X4(r0,r1,r2,r3,addr) \
    asm volatile("ldmatrix.sync.aligned.m8n8.x4.shared.b16 {%0,%1,%2,%3}, [%4];" \
        : "=r"(r0), "=r"(r1), "=r"(r2), "=r"(r3) : "r"(addr))
#define LDSM_X4T(r0,r1,r2,r3,addr) \
    asm volatile("ldmatrix.sync.aligned.m8n8.x4.trans.shared.b16 {%0,%1,%2,%3}, [%4];" \
        : "=r"(r0), "=r"(r1), "=r"(r2), "=r"(r3) : "r"(addr))

// fp16 inputs, fp32 accumulate
#define MMA16816F16(c, a, b) \
    asm volatile("mma.sync.aligned.m16n8k16.row.col.f32.f16.f16.f32 " \
        "{%0,%1,%2,%3}, {%4,%5,%6,%7}, {%8,%9}, {%0,%1,%2,%3};" \
        : "+f"((c)[0]), "+f"((c)[1]), "+f"((c)[2]), "+f"((c)[3]) \
        : "r"((a)[0]), "r"((a)[1]), "r"((a)[2]), "r"((a)[3]), \
          "r"((b)[0]), "r"((b)[1]))

// ============================================================================
// Kernel 1: round x -> fp16 + zero the dst histogram
// ============================================================================
__global__ void convert_kernel(const float* __restrict__ x, int n4, int nnodes) {
    int i = blockIdx.x * blockDim.x + threadIdx.x;
    if (i < nnodes) g_count[i] = 0;
    if (i >= n4) return;
    float4 v = reinterpret_cast<const float4*>(x)[i];
    __half2 h0 = __floats2half2_rn(v.x, v.y);
    __half2 h1 = __floats2half2_rn(v.z, v.w);
    reinterpret_cast<uint2*>(g_xh)[i] =
        make_uint2(*(uint32_t*)&h0, *(uint32_t*)&h1);
}

// ============================================================================
// Kernel 2: histogram edges by DST
// ============================================================================
__global__ void hist_kernel(const int* __restrict__ edst, int E) {
    int i = blockIdx.x * blockDim.x + threadIdx.x;
    if (i < E) atomicAdd(&g_count[edst[i]], 1);
}

// ============================================================================
// Kernel 3: exclusive scan of g_count -> g_off (+ init cursors). 1 block.
// ============================================================================
__global__ __launch_bounds__(1024, 1)
void scan_kernel(int n) {
    __shared__ int ssum[1024];
    const int t = threadIdx.x;
    const int chunk = (n + 1023) >> 10;
    const int lo = t * chunk;
    const int hi = min(lo + chunk, n);

    int s = 0;
    for (int i = lo; i < hi; i++) s += g_count[i];
    ssum[t] = s;
    __syncthreads();

    for (int off = 1; off < 1024; off <<= 1) {
        int u = (t >= off) ? ssum[t - off] : 0;
        __syncthreads();
        if (t >= off) ssum[t] += u;
        __syncthreads();
    }
    int run = ssum[t] - s;
    for (int i = lo; i < hi; i++) {
        g_off[i]    = run;
        g_cursor[i] = run;
        run += g_count[i];
    }
}

// ============================================================================
// Kernel 4: permute edges into dst-sorted order: g_edges[pos] = (src, val)
// ============================================================================
__global__ void fill_kernel(const int*   __restrict__ esrc,
                            const int*   __restrict__ edst,
                            const float* __restrict__ eval_,
                            int E) {
    int i = blockIdx.x * blockDim.x + threadIdx.x;
    if (i >= E) return;
    int d   = edst[i];
    int pos = atomicAdd(&g_cursor[d], 1);
    g_edges[pos] = make_uint2((uint32_t)esrc[i], __float_as_uint(eval_[i]));
}

// ============================================================================
// Kernel 5: persistent GEMM via mma.sync, 2-term fp16 split (W split hi/lo)
//   (m_tile, nh): nh=0 -> d_out = x@W1 + b (fp32) ; nh=1 -> g_yh = x@W2 (fp16)
// ============================================================================
#define GT 256
#define AS_OFF(buf)  ((uint32_t)((buf) * 32768))
#define BS_OFF(hl)   ((uint32_t)(65536 + (hl) * 32768))
#define SM_TOTAL     131072

__device__ __forceinline__ void load_A_tile(uint32_t smem_base, int buf,
                                            int node0, int N, int tid) {
#pragma unroll
    for (int i = 0; i < 8; i++) {
        int idx  = tid + (i << 8);
        int row  = idx >> 4;
        int cc   = idx & 15;
        int node = node0 + row;
        uint32_t sz    = (node < N) ? 16u : 0u;
        uint32_t chunk = (uint32_t)(cc ^ (row & 7));
        uint32_t doff  = (uint32_t)row * 256u + chunk * 16u;
        const __half* sh = g_xh + (size_t)node * D + cc * 8;
        CP_ASYNC16(smem_base + AS_OFF(buf) + doff, sh, sz);
    }
}

__global__ __launch_bounds__(GT, 1)
void gemm_kernel(const float* __restrict__ W,
                 const float* __restrict__ bias,
                 float* __restrict__ out,
                 int N) {
    extern __shared__ char smem[];
    uint32_t smem_base = smem_to_u32(smem);
    const int tid  = threadIdx.x;
    const int lane = tid & 31;
    const int wid  = tid >> 5;
    const int warp_m = (wid & 3) << 5;
    const int warp_n = (wid >> 2) << 6;

    const int num_tiles = (N + 127) >> 7;
    const int total = num_tiles * 2;
    int cur_nh = -1;

    int item = blockIdx.x;
    int buf = 0;
    if (item < total) load_A_tile(smem_base, 0, (item % num_tiles) << 7, N, tid);
    CP_COMMIT();

    for (; item < total; item += gridDim.x) {
        const int m_tile = item % num_tiles;
        const int nh     = item / num_tiles;
        const int node0  = m_tile << 7;

        int next = item + gridDim.x;
        if (next < total)
            load_A_tile(smem_base, buf ^ 1, (next % num_tiles) << 7, N, tid);
        CP_COMMIT();

        if (nh != cur_nh) {
            cur_nh = nh;
#pragma unroll
            for (int j = 0; j < 32; j++) {
                int idx = tid + (j << 8);
                int k   = idx >> 6;
                int n   = (idx & 63) << 1;
                const float* wp = W + ((size_t)(nh * 128 + k)) * 128 + n;
                float w0 = wp[0], w1 = wp[1];
                __half2 h = __floats2half2_rn(w0, w1);
                float q0 = w0 - __half2float(__low2half(h));
                float q1 = w1 - __half2float(__high2half(h));
                __half2 l = __floats2half2_rn(q0, q1);
                uint32_t boff = (uint32_t)k * 256u
                              + (uint32_t)(((n >> 3) ^ (k & 7)) << 4)
                              + (uint32_t)((n & 7) << 1);
                *reinterpret_cast<uint32_t*>(smem + BS_OFF(0) + boff) = *(uint32_t*)&h;
                *reinterpret_cast<uint32_t*>(smem + BS_OFF(1) + boff) = *(uint32_t*)&l;
            }
        }

        CP_WAIT1();
        __syncthreads();

        float acc[2][8][4];
#pragma unroll
        for (int mi = 0; mi < 2; mi++)
#pragma unroll
            for (int ni = 0; ni < 8; ni++)
#pragma unroll
                for (int q = 0; q < 4; q++) acc[mi][ni][q] = 0.f;

#pragma unroll
        for (int ks = 0; ks < 8; ks++) {
            uint32_t ah[2][4];
#pragma unroll
            for (int mi = 0; mi < 2; mi++) {
                int row = warp_m + (mi << 4) + (lane & 15);
                int cb  = (ks << 1) + (lane >> 4);
                uint32_t addr = smem_base + AS_OFF(buf)
                              + (uint32_t)row * 256u
                              + (uint32_t)((cb ^ (row & 7)) << 4);
                LDSM_X4(ah[mi][0], ah[mi][1], ah[mi][2], ah[mi][3], addr);
            }
            uint32_t bh[8][2], bl[8][2];
#pragma unroll
            for (int nj = 0; nj < 4; nj++) {
                int row = (ks << 4) + (lane & 15);
                int cb  = (warp_n >> 3) + (nj << 1) + (lane >> 4);
                uint32_t addr = smem_base + BS_OFF(0)
                              + (uint32_t)row * 256u
                              + (uint32_t)((cb ^ (row & 7)) << 4);
                LDSM_X4T(bh[2*nj][0], bh[2*nj][1], bh[2*nj+1][0], bh[2*nj+1][1], addr);
                LDSM_X4T(bl[2*nj][0], bl[2*nj][1], bl[2*nj+1][0], bl[2*nj+1][1],
                         addr + 32768u);
            }
#pragma unroll
            for (int mi = 0; mi < 2; mi++)
#pragma unroll
                for (int ni = 0; ni < 8; ni++) {
                    MMA16816F16(acc[mi][ni], ah[mi], bh[ni]);
                    MMA16816F16(acc[mi][ni], ah[mi], bl[ni]);
                }
        }

        if (nh == 0) {
#pragma unroll
            for (int ni = 0; ni < 8; ni++) {
                int col = warp_n + (ni << 3) + ((lane & 3) << 1);
                float b0 = bias[col], b1 = bias[col + 1];
#pragma unroll
                for (int mi = 0; mi < 2; mi++) {
                    int r = warp_m + (mi << 4) + (lane >> 2);
                    int node = node0 + r;
                    if (node < N) {
                        float2 v = make_float2(acc[mi][ni][0] + b0, acc[mi][ni][1] + b1);
                        *reinterpret_cast<float2*>(out + (size_t)node * D + col) = v;
                    }
                    int node2 = node + 8;
                    if (node2 < N) {
                        float2 v = make_float2(acc[mi][ni][2] + b0, acc[mi][ni][3] + b1);
                        *reinterpret_cast<float2*>(out + (size_t)node2 * D + col) = v;
                    }
                }
            }
        } else {
#pragma unroll
            for (int ni = 0; ni < 8; ni++) {
                int col = warp_n + (ni << 3) + ((lane & 3) << 1);
#pragma unroll
                for (int mi = 0; mi < 2; mi++) {
                    int r = warp_m + (mi << 4) + (lane >> 2);
                    int node = node0 + r;
                    if (node < N) {
                        __half2 v = __floats2half2_rn(acc[mi][ni][0], acc[mi][ni][1]);
                        *reinterpret_cast<__half2*>(g_yh + (size_t)node * D + col) = v;
                    }
                    int node2 = node + 8;
                    if (node2 < N) {
                        __half2 v = __floats2half2_rn(acc[mi][ni][2], acc[mi][ni][3]);
                        *reinterpret_cast<__half2*>(g_yh + (size_t)node2 * D + col) = v;
                    }
                }
            }
        }
        __syncthreads();
        buf ^= 1;
    }
}

// ============================================================================
// Kernel 6: dst-CSR aggregate, warp per dst row, 8-wide batched gathers:
//   out[d] += sum_e val_e * y[src_e]   (single RMW of out row, NO atomics)
//   Per batch: 8 broadcast edge loads, then 8 independent fp16-row gathers
//   (MLP 8), then 8 FMA steps. acc is outside the load chain.
// ============================================================================
__global__ void aggregate_kernel(float* __restrict__ out, int N) {
    int warp = (blockIdx.x * blockDim.x + threadIdx.x) >> 5;
    int lane = threadIdx.x & 31;
    if (warp >= N) return;

    int cnt = g_count[warp];
    if (cnt == 0) return;
    int e   = g_off[warp];
    const int end = e + cnt;

    const uint2* y2 = reinterpret_cast<const uint2*>(g_yh);  // 8B = 4 halves/lane
    float2 acc0 = make_float2(0.f, 0.f);
    float2 acc1 = make_float2(0.f, 0.f);

    while (e + 8 <= end) {
        uint2 ed[8];
#pragma unroll
        for (int i = 0; i < 8; i++) ed[i] = g_edges[e + i];
        uint2 w[8];
#pragma unroll
        for (int i = 0; i < 8; i++)
            w[i] = y2[(size_t)ed[i].x * 32 + lane];
#pragma unroll
        for (int i = 0; i < 8; i++) {
            float v = __uint_as_float(ed[i].y);
            float2 f0 = __half22float2(*reinterpret_cast<__half2*>(&w[i].x));
            float2 f1 = __half22float2(*reinterpret_cast<__half2*>(&w[i].y));
            acc0.x += v * f0.x; acc0.y += v * f0.y;
            acc1.x += v * f1.x; acc1.y += v * f1.y;
        }
        e += 8;
    }
    // remainder (0..7 edges)
    {
        int rem = end - e;
        uint2 ed[7];
#pragma unroll
        for (int i = 0; i < 7; i++)
            if (i < rem) ed[i] = g_edges[e + i];
        uint2 w[7];
#pragma unroll
        for (int i = 0; i < 7; i++)
            if (i < rem) w[i] = y2[(size_t)ed[i].x * 32 + lane];
#pragma unroll
        for (int i = 0; i < 7; i++)
            if (i < rem) {
                float v = __uint_as_float(ed[i].y);
                float2 f0 = __half22float2(*reinterpret_cast<__half2*>(&w[i].x));
                float2 f1 = __half22float2(*reinterpret_cast<__half2*>(&w[i].y));
                acc0.x += v * f0.x; acc0.y += v * f0.y;
                acc1.x += v * f1.x; acc1.y += v * f1.y;
            }
    }

    float4* po = reinterpret_cast<float4*>(out) + (size_t)warp * 32 + lane;
    float4 o = *po;
    o.x += acc0.x; o.y += acc0.y; o.z += acc1.x; o.w += acc1.y;
    *po = o;
}

// ============================================================================
// Launch
// ============================================================================
extern "C" void kernel_launch(void* const* d_in, const int* in_sizes, int n_in,
                              void* d_out, int out_size) {
    const float* x     = (const float*)d_in[0];
    const int*   esrc  = (const int*)  d_in[1];
    const int*   edst  = (const int*)  d_in[2];
    const float* eval_ = (const float*)d_in[3];
    const float* W     = (const float*)d_in[4];
    const float* bias  = (const float*)d_in[5];
    float*       out   = (float*)d_out;

    const int N = in_sizes[0] / D;     // 100000
    const int E = in_sizes[1];         // 1600000

    // 1) round x -> fp16, zero dst histogram
    {
        int n4 = N * (D / 4);
        convert_kernel<<<(n4 + 255) / 256, 256>>>(x, n4, N);
    }
    // 2) dst-CSR build
    hist_kernel<<<(E + 255) / 256, 256>>>(edst, E);
    scan_kernel<<<1, 1024>>>(N);
    fill_kernel<<<(E + 255) / 256, 256>>>(esrc, edst, eval_, E);
    // 3) persistent GEMM: d_out = x@W1 + b ; g_yh = fp16(x@W2)
    {
        static bool attr_set = false;
        if (!attr_set) {
            cudaFuncSetAttribute(gemm_kernel,
                                 cudaFuncAttributeMaxDynamicSharedMemorySize,
                                 SM_TOTAL);
            attr_set = true;
        }
        gemm_kernel<<<148, GT, SM_TOTAL>>>(W, bias, out, N);
    }
    // 4) aggregate (warp per dst, no atomics)
    aggregate_kernel<<<(N * 32 + 255) / 256, 256>>>(out, N);
}

// round 10
// speedup vs baseline: 1.2476x; 1.2476x over previous
#include <cuda_runtime.h>
#include <cuda_fp16.h>
#include <cstdint>

#define D      128      // D_IN = D_OUT
#define NMAX   100000

// Scratch (device globals; no allocation allowed)
__device__ __half g_xh[NMAX * D];   // x rounded to fp16 (GEMM A operand)
__device__ float  g_y [NMAX * D];   // y = x @ W2 (fp32)

// ============================================================================
// PTX helpers (base ISA: cp.async / ldmatrix / mma.sync)
// ============================================================================
__device__ __forceinline__ uint32_t smem_to_u32(const void* p) {
    uint32_t a;
    asm("{ .reg .u64 t; cvta.to.shared.u64 t, %1; cvt.u32.u64 %0, t; }"
        : "=r"(a) : "l"(p));
    return a;
}
#define CP_ASYNC16(dst, src, sz) \
    asm volatile("cp.async.cg.shared.global [%0], [%1], 16, %2;" \
        :: "r"(dst), "l"(src), "r"(sz))
#define CP_COMMIT() asm volatile("cp.async.commit_group;" ::: "memory")
#define CP_WAIT1()  asm volatile("cp.async.wait_group 1;"  ::: "memory")

#define LDSM_X4(r0,r1,r2,r3,addr) \
    asm volatile("ldmatrix.sync.aligned.m8n8.x4.shared.b16 {%0,%1,%2,%3}, [%4];" \
        : "=r"(r0), "=r"(r1), "=r"(r2), "=r"(r3) : "r"(addr))
#define LDSM_X4T(r0,r1,r2,r3,addr) \
    asm volatile("ldmatrix.sync.aligned.m8n8.x4.trans.shared.b16 {%0,%1,%2,%3}, [%4];" \
        : "=r"(r0), "=r"(r1), "=r"(r2), "=r"(r3) : "r"(addr))

// fp16 inputs, fp32 accumulate
#define MMA16816F16(c, a, b) \
    asm volatile("mma.sync.aligned.m16n8k16.row.col.f32.f16.f16.f32 " \
        "{%0,%1,%2,%3}, {%4,%5,%6,%7}, {%8,%9}, {%0,%1,%2,%3};" \
        : "+f"((c)[0]), "+f"((c)[1]), "+f"((c)[2]), "+f"((c)[3]) \
        : "r"((a)[0]), "r"((a)[1]), "r"((a)[2]), "r"((a)[3]), \
          "r"((b)[0]), "r"((b)[1]))

// ============================================================================
// Kernel 1: round x -> fp16 (one pass)
// ============================================================================
__global__ void convert_kernel(const float* __restrict__ x, int n4) {
    int i = blockIdx.x * blockDim.x + threadIdx.x;
    if (i >= n4) return;
    float4 v = reinterpret_cast<const float4*>(x)[i];
    __half2 h0 = __floats2half2_rn(v.x, v.y);
    __half2 h1 = __floats2half2_rn(v.z, v.w);
    reinterpret_cast<uint2*>(g_xh)[i] =
        make_uint2(*(uint32_t*)&h0, *(uint32_t*)&h1);
}

// ============================================================================
// Kernel 2: persistent MERGED GEMM via mma.sync, 2-term fp16 split.
//   Per m_tile: load A once, then compute BOTH
//     out = A @ W1(hi/lo) + b   and   g_y = A @ W2(hi/lo)
//   SMEM: A double-buffered (2 x 32KB) + B both halves hi/lo (4 x 32KB) = 192KB
// ============================================================================
#define GT 256
#define AS_OFF(buf)     ((uint32_t)((buf) * 32768))
#define BS_OFF(nh,hl)   ((uint32_t)(65536 + ((nh) * 2 + (hl)) * 32768))
#define SM_TOTAL        196608

__device__ __forceinline__ void load_A_tile(uint32_t smem_base, int buf,
                                            int node0, int N, int tid) {
#pragma unroll
    for (int i = 0; i < 8; i++) {
        int idx  = tid + (i << 8);        // 0..2047 16B chunks
        int row  = idx >> 4;              // 0..127
        int cc   = idx & 15;              // chunk within row (8 fp16 each)
        int node = node0 + row;
        uint32_t sz    = (node < N) ? 16u : 0u;
        uint32_t chunk = (uint32_t)(cc ^ (row & 7));
        uint32_t doff  = (uint32_t)row * 256u + chunk * 16u;
        const __half* sh = g_xh + (size_t)node * D + cc * 8;
        CP_ASYNC16(smem_base + AS_OFF(buf) + doff, sh, sz);
    }
}

__global__ __launch_bounds__(GT, 1)
void gemm_kernel(const float* __restrict__ W,
                 const float* __restrict__ bias,
                 float* __restrict__ out,
                 int N) {
    extern __shared__ char smem[];
    uint32_t smem_base = smem_to_u32(smem);
    const int tid  = threadIdx.x;
    const int lane = tid & 31;
    const int wid  = tid >> 5;
    const int warp_m = (wid & 3) << 5;
    const int warp_n = (wid >> 2) << 6;

    const int num_tiles = (N + 127) >> 7;

    // ---- load BOTH B halves (W1, W2) split into fp16 hi/lo, once ----
#pragma unroll
    for (int nh = 0; nh < 2; nh++) {
#pragma unroll
        for (int j = 0; j < 32; j++) {
            int idx = tid + (j << 8);          // 0..8191 (half2 pairs)
            int k   = idx >> 6;                // 0..127
            int n   = (idx & 63) << 1;         // even col
            const float* wp = W + ((size_t)(nh * 128 + k)) * 128 + n;
            float w0 = wp[0], w1 = wp[1];
            __half2 h = __floats2half2_rn(w0, w1);
            float q0 = w0 - __half2float(__low2half(h));
            float q1 = w1 - __half2float(__high2half(h));
            __half2 l = __floats2half2_rn(q0, q1);
            uint32_t boff = (uint32_t)k * 256u
                          + (uint32_t)(((n >> 3) ^ (k & 7)) << 4)
                          + (uint32_t)((n & 7) << 1);
            *reinterpret_cast<uint32_t*>(smem + BS_OFF(nh, 0) + boff) = *(uint32_t*)&h;
            *reinterpret_cast<uint32_t*>(smem + BS_OFF(nh, 1) + boff) = *(uint32_t*)&l;
        }
    }

    int item = blockIdx.x;
    int buf = 0;
    if (item < num_tiles) load_A_tile(smem_base, 0, item << 7, N, tid);
    CP_COMMIT();

    for (; item < num_tiles; item += gridDim.x) {
        const int node0 = item << 7;

        int next = item + gridDim.x;
        if (next < num_tiles)
            load_A_tile(smem_base, buf ^ 1, next << 7, N, tid);
        CP_COMMIT();
        CP_WAIT1();
        __syncthreads();     // A(buf) ready (B loaded before first sync path too)

        // ---- two output matrices from the SAME A tile ----
#pragma unroll
        for (int nh = 0; nh < 2; nh++) {
            float acc[2][8][4];
#pragma unroll
            for (int mi = 0; mi < 2; mi++)
#pragma unroll
                for (int ni = 0; ni < 8; ni++)
#pragma unroll
                    for (int q = 0; q < 4; q++) acc[mi][ni][q] = 0.f;

#pragma unroll
            for (int ks = 0; ks < 8; ks++) {
                uint32_t ah[2][4];
#pragma unroll
                for (int mi = 0; mi < 2; mi++) {
                    int row = warp_m + (mi << 4) + (lane & 15);
                    int cb  = (ks << 1) + (lane >> 4);
                    uint32_t addr = smem_base + AS_OFF(buf)
                                  + (uint32_t)row * 256u
                                  + (uint32_t)((cb ^ (row & 7)) << 4);
                    LDSM_X4(ah[mi][0], ah[mi][1], ah[mi][2], ah[mi][3], addr);
                }
                uint32_t bh[8][2], bl[8][2];
#pragma unroll
                for (int nj = 0; nj < 4; nj++) {
                    int row = (ks << 4) + (lane & 15);
                    int cb  = (warp_n >> 3) + (nj << 1) + (lane >> 4);
                    uint32_t soff = (uint32_t)row * 256u
                                  + (uint32_t)((cb ^ (row & 7)) << 4);
                    uint32_t addr = smem_base + BS_OFF(nh, 0) + soff;
                    LDSM_X4T(bh[2*nj][0], bh[2*nj][1], bh[2*nj+1][0], bh[2*nj+1][1],
                             addr);
                    LDSM_X4T(bl[2*nj][0], bl[2*nj][1], bl[2*nj+1][0], bl[2*nj+1][1],
                             addr + 32768u);
                }
#pragma unroll
                for (int mi = 0; mi < 2; mi++)
#pragma unroll
                    for (int ni = 0; ni < 8; ni++) {
                        MMA16816F16(acc[mi][ni], ah[mi], bh[ni]);   // A*Bh
                        MMA16816F16(acc[mi][ni], ah[mi], bl[ni]);   // A*Bl
                    }
            }

            // ---- epilogue ----
            float* dst = (nh == 0) ? out : g_y;
#pragma unroll
            for (int ni = 0; ni < 8; ni++) {
                int col = warp_n + (ni << 3) + ((lane & 3) << 1);
                float b0 = 0.f, b1 = 0.f;
                if (nh == 0) { b0 = bias[col]; b1 = bias[col + 1]; }
#pragma unroll
                for (int mi = 0; mi < 2; mi++) {
                    int r = warp_m + (mi << 4) + (lane >> 2);
                    int node = node0 + r;
                    if (node < N) {
                        float2 v = make_float2(acc[mi][ni][0] + b0,
                                               acc[mi][ni][1] + b1);
                        *reinterpret_cast<float2*>(dst + (size_t)node * D + col) = v;
                    }
                    int node2 = node + 8;
                    if (node2 < N) {
                        float2 v = make_float2(acc[mi][ni][2] + b0,
                                               acc[mi][ni][3] + b1);
                        *reinterpret_cast<float2*>(dst + (size_t)node2 * D + col) = v;
                    }
                }
            }
        }
        __syncthreads();     // protect A(buf) before refill next iter
        buf ^= 1;
    }
}

// ============================================================================
// Kernel 3: edge scatter (warp per edge — proven shape):
//   out[dst] += val * y[src]  via red.global.add.v4.f32
// ============================================================================
__global__ void scatter_kernel(const int*   __restrict__ esrc,
                               const int*   __restrict__ edst,
                               const float* __restrict__ eval_,
                               float* __restrict__ out,
                               int E) {
    int warp = (blockIdx.x * blockDim.x + threadIdx.x) >> 5;
    int lane = threadIdx.x & 31;
    if (warp >= E) return;

    int   s = esrc[warp];
    int   d = edst[warp];
    float v = eval_[warp];

    const float4* ys = reinterpret_cast<const float4*>(g_y) + (size_t)s * (D / 4);
    float4 yv = ys[lane];

    float* p = out + (size_t)d * D + lane * 4;
    asm volatile("red.global.add.v4.f32 [%0], {%1, %2, %3, %4};"
                 :: "l"(p), "f"(yv.x * v), "f"(yv.y * v),
                    "f"(yv.z * v), "f"(yv.w * v)
                 : "memory");
}

// ============================================================================
// Launch
// ============================================================================
extern "C" void kernel_launch(void* const* d_in, const int* in_sizes, int n_in,
                              void* d_out, int out_size) {
    const float* x     = (const float*)d_in[0];
    const int*   esrc  = (const int*)  d_in[1];
    const int*   edst  = (const int*)  d_in[2];
    const float* eval_ = (const float*)d_in[3];
    const float* W     = (const float*)d_in[4];
    const float* bias  = (const float*)d_in[5];
    float*       out   = (float*)d_out;

    const int N = in_sizes[0] / D;     // 100000
    const int E = in_sizes[1];         // 1600000

    // 1) round x -> fp16
    {
        int n4 = N * (D / 4);
        convert_kernel<<<(n4 + 255) / 256, 256>>>(x, n4);
    }
    // 2) merged persistent GEMM: d_out = x@W1 + b ; g_y = x@W2
    {
        static bool attr_set = false;
        if (!attr_set) {
            cudaFuncSetAttribute(gemm_kernel,
                                 cudaFuncAttributeMaxDynamicSharedMemorySize,
                                 SM_TOTAL);
            attr_set = true;
        }
        gemm_kernel<<<148, GT, SM_TOTAL>>>(W, bias, out, N);
    }
    // 3) scatter-add edges into d_out (warp per edge)
    {
        int blocks = (E + 7) / 8;      // 8 warps (256 thr) per block
        scatter_kernel<<<blocks, 256>>>(esrc, edst, eval_, out, E);
    }
}